// round 1
// baseline (speedup 1.0000x reference)
#include <cuda_runtime.h>
#include <cuda_bf16.h>
#include <math.h>

// Problem constants
#define BB 2
#define EE 1024
#define SS 2048
#define HH 16
#define DD 64
#define BES (BB*EE*SS)          // 4,194,304 elements

// ---------------------------------------------------------------------------
// Scratch (device globals; no runtime allocation allowed)
// ---------------------------------------------------------------------------
__device__ float g_ql[BES], g_kl[BES], g_vl[BES];
__device__ float g_qr[BES], g_kr[BES], g_vr[BES];
__device__ float g_al[BES], g_ar[BES];
__device__ float g_lnout[BES], g_y[BES];
__device__ float g_h1[2 * BES];
__device__ float g_lam;

// ---------------------------------------------------------------------------
// GEMM: C[b][m][n] = relu?(alpha * sum_k W[m][k] * X[b][k][n] + bias[m])
// W row-major [M,K]; X [B,K,N] (n contiguous); C [B,M,N] (n contiguous)
// 128x128 block tile, BK=16, 256 threads, 8x8 per thread.
// ---------------------------------------------------------------------------
__global__ __launch_bounds__(256) void gemm_kernel(
    const float* __restrict__ W, const float* __restrict__ X,
    float* __restrict__ C, int M, int K, int N,
    const float* __restrict__ bias, float alpha, int relu)
{
    __shared__ float As[16][128];   // transposed W tile: As[k][m]
    __shared__ float Bs[16][128];   // X tile: Bs[k][n]

    const int tid = threadIdx.x;
    const int bm = blockIdx.y << 7;
    const int bn = blockIdx.x << 7;
    const float* Xb = X + (size_t)blockIdx.z * K * N;
    float* Cb = C + (size_t)blockIdx.z * M * N;

    const int tx = tid & 15, ty = tid >> 4;
    const int wrow = tid >> 1;            // W tile row this thread loads
    const int wk0  = (tid & 1) << 3;      // k-offset 0 or 8 (8 floats each)
    const int xk   = tid >> 4;            // X tile row
    const int xn0  = (tid & 15) << 3;     // n-offset, 8 floats each

    float acc[8][8];
#pragma unroll
    for (int i = 0; i < 8; ++i)
#pragma unroll
        for (int j = 0; j < 8; ++j) acc[i][j] = 0.f;

    for (int k0 = 0; k0 < K; k0 += 16) {
        // --- load tiles ---
        const float* wp = W + (size_t)(bm + wrow) * K + k0 + wk0;
        float4 w0 = *(const float4*)wp;
        float4 w1 = *(const float4*)(wp + 4);
        As[wk0 + 0][wrow] = w0.x; As[wk0 + 1][wrow] = w0.y;
        As[wk0 + 2][wrow] = w0.z; As[wk0 + 3][wrow] = w0.w;
        As[wk0 + 4][wrow] = w1.x; As[wk0 + 5][wrow] = w1.y;
        As[wk0 + 6][wrow] = w1.z; As[wk0 + 7][wrow] = w1.w;

        const float* xp = Xb + (size_t)(k0 + xk) * N + bn + xn0;
        *(float4*)&Bs[xk][xn0]     = *(const float4*)xp;
        *(float4*)&Bs[xk][xn0 + 4] = *(const float4*)(xp + 4);
        __syncthreads();

        // --- compute ---
#pragma unroll
        for (int k = 0; k < 16; ++k) {
            float4 a0 = *(const float4*)&As[k][ty << 2];
            float4 a1 = *(const float4*)&As[k][(ty << 2) + 64];
            float4 b0 = *(const float4*)&Bs[k][tx << 2];
            float4 b1 = *(const float4*)&Bs[k][(tx << 2) + 64];
            float ar8[8] = {a0.x, a0.y, a0.z, a0.w, a1.x, a1.y, a1.z, a1.w};
            float br8[8] = {b0.x, b0.y, b0.z, b0.w, b1.x, b1.y, b1.z, b1.w};
#pragma unroll
            for (int i = 0; i < 8; ++i)
#pragma unroll
                for (int j = 0; j < 8; ++j)
                    acc[i][j] = fmaf(ar8[i], br8[j], acc[i][j]);
        }
        __syncthreads();
    }

    // --- epilogue ---
#pragma unroll
    for (int i = 0; i < 8; ++i) {
        const int m = bm + (ty << 2) + (i & 3) + ((i >> 2) << 6);
        const float bv = bias ? bias[m] : 0.f;
        float r[8];
#pragma unroll
        for (int j = 0; j < 8; ++j) {
            float v = alpha * acc[i][j] + bv;
            r[j] = relu ? fmaxf(v, 0.f) : v;
        }
        float4 o0 = {r[0], r[1], r[2], r[3]};
        float4 o1 = {r[4], r[5], r[6], r[7]};
        float* cp = Cb + (size_t)m * N + bn + (tx << 2);
        *(float4*)cp = o0;
        *(float4*)(cp + 64) = o1;
    }
}

// ---------------------------------------------------------------------------
// Flash attention (causal), fp32. Q/K/V/O stored [B, E, S] (s contiguous),
// head h occupies rows h*D .. h*D+63. One block = 128 query rows of one (b,h);
// one thread owns one query row. Key tile Bc=64.
// SMEM: Qs[64][128] | Ks[64][64] | Vt[64][68] (transposed, padded) | Ps[64][128]
// ---------------------------------------------------------------------------
#define ATTN_SMEM ((64*128 + 64*64 + 64*68 + 64*128) * 4)

__global__ __launch_bounds__(128) void attn_kernel(
    const float* __restrict__ Q, const float* __restrict__ Kg,
    const float* __restrict__ V, float* __restrict__ O)
{
    extern __shared__ float sm[];
    float* Qs = sm;                  // [64][128]  Qs[d][q_local]
    float* Ks = sm + 64 * 128;       // [64][64]   Ks[d][t]
    float* Vt = Ks + 64 * 64;        // [64][68]   Vt[t][d] (pad 68)
    float* Ps = Vt + 64 * 68;        // [64][128]  Ps[t][q_local]

    const int tid = threadIdx.x;
    const int qt = (gridDim.x - 1) - blockIdx.x;   // heavy tiles launch first
    const int q0 = qt << 7;
    const size_t base = ((size_t)blockIdx.z * EE + (size_t)blockIdx.y * DD) * SS;
    const float* Qp = Q + base;
    const float* Kp = Kg + base;
    const float* Vp = V + base;
    const int q = q0 + tid;          // this thread's global query index

    // load Q tile (scaling already folded into the projection GEMM)
    for (int f = tid; f < 64 * 32; f += 128) {
        int d = f >> 5, qc = (f & 31) << 2;
        *(float4*)&Qs[d * 128 + qc] =
            *(const float4*)&Qp[(size_t)d * SS + q0 + qc];
    }

    float o[64];
#pragma unroll
    for (int d = 0; d < 64; ++d) o[d] = 0.f;
    float mrow = -1e30f, lrow = 0.f;

    const int nt = qt * 2 + 2;       // causal: key tiles covering t < q0+128
    for (int kt = 0; kt < nt; ++kt) {
        const int t0 = kt << 6;
        __syncthreads();             // also guards Q-tile load on kt==0
        // K tile (natural) + V tile (transposed, padded 68)
        for (int f = tid; f < 64 * 16; f += 128) {
            int d = f >> 4, tc = (f & 15) << 2;
            *(float4*)&Ks[d * 64 + tc] =
                *(const float4*)&Kp[(size_t)d * SS + t0 + tc];
        }
        for (int f = tid; f < 64 * 64; f += 128) {
            int d = f >> 6, tt = f & 63;
            Vt[tt * 68 + d] = Vp[(size_t)d * SS + t0 + tt];
        }
        __syncthreads();

        // scores: s[t] = sum_d Q[d][q] * K[d][t]  (Ks reads are uniform-broadcast)
        float s[64];
#pragma unroll
        for (int t = 0; t < 64; ++t) s[t] = 0.f;
#pragma unroll 4
        for (int d = 0; d < 64; ++d) {
            float qd = Qs[d * 128 + tid];
#pragma unroll
            for (int t4 = 0; t4 < 16; ++t4) {
                float4 k4 = *(const float4*)&Ks[d * 64 + (t4 << 2)];
                s[(t4 << 2) + 0] = fmaf(qd, k4.x, s[(t4 << 2) + 0]);
                s[(t4 << 2) + 1] = fmaf(qd, k4.y, s[(t4 << 2) + 1]);
                s[(t4 << 2) + 2] = fmaf(qd, k4.z, s[(t4 << 2) + 2]);
                s[(t4 << 2) + 3] = fmaf(qd, k4.w, s[(t4 << 2) + 3]);
            }
        }
        // causal mask
#pragma unroll
        for (int t = 0; t < 64; ++t)
            if (t0 + t > q) s[t] = -1e30f;

        // online softmax (row fully owned by this thread: no reductions)
        float mx = mrow;
#pragma unroll
        for (int t = 0; t < 64; ++t) mx = fmaxf(mx, s[t]);
        float corr = __expf(mrow - mx);
        mrow = mx;
        lrow *= corr;
#pragma unroll
        for (int d = 0; d < 64; ++d) o[d] *= corr;
        float lsum = 0.f;
#pragma unroll
        for (int t = 0; t < 64; ++t) {
            float p = __expf(s[t] - mx);
            Ps[t * 128 + tid] = p;   // stage P so the t-loop below stays rolled
            lsum += p;
        }
        lrow += lsum;

        // O accumulation: o[d] += P[t] * V[t][d]  (Vt reads uniform-broadcast)
        for (int t = 0; t < 64; ++t) {
            float pt = Ps[t * 128 + tid];
#pragma unroll
            for (int d4 = 0; d4 < 16; ++d4) {
                float4 v4 = *(const float4*)&Vt[t * 68 + (d4 << 2)];
                o[(d4 << 2) + 0] = fmaf(pt, v4.x, o[(d4 << 2) + 0]);
                o[(d4 << 2) + 1] = fmaf(pt, v4.y, o[(d4 << 2) + 1]);
                o[(d4 << 2) + 2] = fmaf(pt, v4.z, o[(d4 << 2) + 2]);
                o[(d4 << 2) + 3] = fmaf(pt, v4.w, o[(d4 << 2) + 3]);
            }
        }
    }

    const float inv = 1.f / lrow;
    float* Op = O + base;
#pragma unroll
    for (int d = 0; d < 64; ++d)
        Op[(size_t)d * SS + q] = o[d] * inv;
}

// ---------------------------------------------------------------------------
// lambda = exp(sum lam_q_l*lam_k_l) - exp(sum lam_q_r*lam_k_r) + 0.1
// ---------------------------------------------------------------------------
__global__ void lam_kernel(const float* __restrict__ ql, const float* __restrict__ kl,
                           const float* __restrict__ qr, const float* __restrict__ kr)
{
    const int t = threadIdx.x;   // 32 threads
    float a = ql[t] * kl[t] + ql[t + 32] * kl[t + 32];
    float b = qr[t] * kr[t] + qr[t + 32] * kr[t + 32];
#pragma unroll
    for (int off = 16; off > 0; off >>= 1) {
        a += __shfl_xor_sync(0xffffffffu, a, off);
        b += __shfl_xor_sync(0xffffffffu, b, off);
    }
    if (t == 0) g_lam = expf(a) - expf(b) + 0.1f;
}

// ---------------------------------------------------------------------------
// combined = attn_l - lam*attn_r; LayerNorm over E (biased var, eps 1e-5).
// Data is [B,E,S]; thread <-> s gives coalesced access; e-dim split 16 ways.
// Block: 512 threads = 16 e-groups x 32 s. Grid: B*S/32 = 128 blocks.
// ---------------------------------------------------------------------------
__global__ __launch_bounds__(512) void ln_kernel(
    const float* __restrict__ al, const float* __restrict__ ar,
    const float* __restrict__ gg, const float* __restrict__ bbv,
    float* __restrict__ out)
{
    __shared__ float ps[16][32], pq[16][32], smu[32], srs[32];
    const int tid = threadIdx.x;
    const int ty = tid >> 5, sl = tid & 31;
    const int b = blockIdx.x >> 6;                 // S/32 = 64 s-blocks/batch
    const int s = ((blockIdx.x & 63) << 5) + sl;
    const float lam = g_lam;
    const size_t col = (size_t)b * EE * SS + s;
    const int e0 = ty << 6;                        // 64 e's per group

    float sum = 0.f, sq = 0.f;
    for (int e = e0; e < e0 + 64; ++e) {
        size_t idx = col + (size_t)e * SS;
        float c = al[idx] - lam * ar[idx];
        sum += c; sq += c * c;
    }
    ps[ty][sl] = sum; pq[ty][sl] = sq;
    __syncthreads();
    if (ty == 0) {
        float ts = 0.f, tq = 0.f;
#pragma unroll
        for (int r = 0; r < 16; ++r) { ts += ps[r][sl]; tq += pq[r][sl]; }
        float mu = ts * (1.f / EE);
        float var = tq * (1.f / EE) - mu * mu;
        smu[sl] = mu;
        srs[sl] = rsqrtf(var + 1e-5f);
    }
    __syncthreads();
    const float mu = smu[sl], rs = srs[sl];
    for (int e = e0; e < e0 + 64; ++e) {
        size_t idx = col + (size_t)e * SS;
        float c = al[idx] - lam * ar[idx];
        out[idx] = (c - mu) * rs * gg[e] + bbv[e];
    }
}

// ---------------------------------------------------------------------------
// Launch
// ---------------------------------------------------------------------------
static float* sym_addr(const void* symbol)
{
    void* p = nullptr;
    cudaGetSymbolAddress(&p, symbol);
    return (float*)p;
}

extern "C" void kernel_launch(void* const* d_in, const int* in_sizes, int n_in,
                              void* d_out, int out_size)
{
    const float* left  = (const float*)d_in[0];
    const float* right = (const float*)d_in[1];
    const float* Wq_l  = (const float*)d_in[2];
    const float* Wk_l  = (const float*)d_in[3];
    const float* Wv_l  = (const float*)d_in[4];
    const float* Wq_r  = (const float*)d_in[5];
    const float* Wk_r  = (const float*)d_in[6];
    const float* Wv_r  = (const float*)d_in[7];
    const float* Wo    = (const float*)d_in[8];
    const float* lql   = (const float*)d_in[9];
    const float* lkl   = (const float*)d_in[10];
    const float* lqr   = (const float*)d_in[11];
    const float* lkr   = (const float*)d_in[12];
    const float* ln_g  = (const float*)d_in[13];
    const float* ln_b  = (const float*)d_in[14];
    const float* W1    = (const float*)d_in[15];
    const float* b1    = (const float*)d_in[16];
    const float* W2    = (const float*)d_in[17];
    const float* b2    = (const float*)d_in[18];
    float* out = (float*)d_out;

    float* ql = sym_addr(g_ql); float* kl = sym_addr(g_kl); float* vl = sym_addr(g_vl);
    float* qr = sym_addr(g_qr); float* kr = sym_addr(g_kr); float* vr = sym_addr(g_vr);
    float* al = sym_addr(g_al); float* ar = sym_addr(g_ar);
    float* lno = sym_addr(g_lnout); float* y = sym_addr(g_y);
    float* h1 = sym_addr(g_h1);

    const float qscale = 0.125f;   // D^-0.5 folded into q projection

    dim3 blk(256);
    dim3 gp(SS / 128, EE / 128, BB);         // (16, 8, 2)
    dim3 gp1(SS / 128, (2 * EE) / 128, BB);  // (16, 16, 2)

    // QKV projections (native [B,E,S] layout -> no transposes anywhere)
    gemm_kernel<<<gp, blk>>>(Wq_l, left,  ql, EE, EE, SS, nullptr, qscale, 0);
    gemm_kernel<<<gp, blk>>>(Wk_l, left,  kl, EE, EE, SS, nullptr, 1.f, 0);
    gemm_kernel<<<gp, blk>>>(Wv_l, left,  vl, EE, EE, SS, nullptr, 1.f, 0);
    gemm_kernel<<<gp, blk>>>(Wq_r, right, qr, EE, EE, SS, nullptr, qscale, 0);
    gemm_kernel<<<gp, blk>>>(Wk_r, right, kr, EE, EE, SS, nullptr, 1.f, 0);
    gemm_kernel<<<gp, blk>>>(Wv_r, right, vr, EE, EE, SS, nullptr, 1.f, 0);

    // attention (both paths)
    cudaFuncSetAttribute(attn_kernel, cudaFuncAttributeMaxDynamicSharedMemorySize,
                         ATTN_SMEM);
    dim3 ga(SS / 128, HH, BB);               // (16, 16, 2)
    attn_kernel<<<ga, 128, ATTN_SMEM>>>(ql, kl, vl, al);
    attn_kernel<<<ga, 128, ATTN_SMEM>>>(qr, kr, vr, ar);

    // lambda, combine + LN
    lam_kernel<<<1, 32>>>(lql, lkl, lqr, lkr);
    ln_kernel<<<BB * (SS / 32), 512>>>(al, ar, ln_g, ln_b, lno);

    // output projection + MLP (W2 writes straight into d_out, already [B,E,S])
    gemm_kernel<<<gp,  blk>>>(Wo, lno, y,   EE,     EE,     SS, nullptr, 1.f, 0);
    gemm_kernel<<<gp1, blk>>>(W1, y,   h1,  2 * EE, EE,     SS, b1,      1.f, 1);
    gemm_kernel<<<gp,  blk>>>(W2, h1,  out, EE,     2 * EE, SS, b2,      1.f, 0);
}

// round 3
// speedup vs baseline: 1.0649x; 1.0649x over previous
#include <cuda_runtime.h>
#include <math.h>

// Problem constants
#define BB 2
#define EE 1024
#define SS 2048
#define HH 16
#define DD 64
#define BES (BB*EE*SS)          // 4,194,304 elements

// ---------------------------------------------------------------------------
// Scratch (device globals; no runtime allocation allowed)
// ---------------------------------------------------------------------------
__device__ float g_ql[BES], g_kl[BES], g_vl[BES];
__device__ float g_qr[BES], g_kr[BES], g_vr[BES];
__device__ float g_al[BES], g_ar[BES];
__device__ float g_lnout[BES], g_y[BES];
__device__ float g_h1[2 * BES];
__device__ float g_lam;

// ---------------------------------------------------------------------------
// TF32 helpers
// ---------------------------------------------------------------------------
__device__ __forceinline__ unsigned f2tf32(float v) {
    unsigned r; asm("cvt.rna.tf32.f32 %0, %1;" : "=r"(r) : "f"(v)); return r;
}
__device__ __forceinline__ void mma_tf32(
    float& c0, float& c1, float& c2, float& c3,
    unsigned a0, unsigned a1, unsigned a2, unsigned a3,
    unsigned b0, unsigned b1)
{
    asm("mma.sync.aligned.m16n8k8.row.col.f32.tf32.tf32.f32 "
        "{%0,%1,%2,%3}, {%4,%5,%6,%7}, {%8,%9}, {%0,%1,%2,%3};"
        : "+f"(c0), "+f"(c1), "+f"(c2), "+f"(c3)
        : "r"(a0), "r"(a1), "r"(a2), "r"(a3), "r"(b0), "r"(b1));
}

// ---------------------------------------------------------------------------
// Tensor-core GEMM (3xTF32): C[b][m][n] = relu?(alpha*sum_k W[m][k]*X[b][k][n] + bias[m])
// Block tile 128x128, BK=16, 256 threads = 8 warps (2 warpM x 4 warpN),
// warp tile 64x32 = 4x4 m16n8k8 tiles. Fragments staged in SMEM in
// fragment order -> conflict-free LDS.128/LDS.64 reads, contiguous STS writes.
//
// m16n8k8 tf32 fragment layouts (PTX ISA):
//   A (row-major 16x8): a0=(r,c) a1=(r+8,c) a2=(r,c+4) a3=(r+8,c+4); r=lane>>2, c=lane&3
//   B (col-major 8x8):  b0=(k,n) b1=(k+4,n);                        k=lane&3, n=lane>>2
//   C (row-major 16x8): c0=(r,2j) c1=(r,2j+1) c2=(r+8,2j) c3=(r+8,2j+1); j=lane&3
// ---------------------------------------------------------------------------
__global__ __launch_bounds__(256, 1) void gemm_tc(
    const float* __restrict__ W, const float* __restrict__ X,
    float* __restrict__ C, int M, int K, int N,
    const float* __restrict__ bias, float alpha, int relu)
{
    // fragment-order smem: A slots = 8mt*2ks*32lane, 4 regs each; B slots *2 regs
    __shared__ __align__(16) unsigned Ah[8 * 2 * 32 * 4];
    __shared__ __align__(16) float    Al[8 * 2 * 32 * 4];
    __shared__ __align__(16) unsigned Bh[16 * 2 * 32 * 2];
    __shared__ __align__(16) float    Bl[16 * 2 * 32 * 2];

    const int t = threadIdx.x;
    const int lane = t & 31, wid = t >> 5;
    const int warpM = wid >> 2, warpN = wid & 3;
    const int bm = blockIdx.y << 7, bn = blockIdx.x << 7;
    const float* Xb = X + (size_t)blockIdx.z * K * N;
    float* Cb = C + (size_t)blockIdx.z * M * N;

    float acc[4][4][4];   // [mt][nt][creg]
#pragma unroll
    for (int a = 0; a < 4; ++a)
#pragma unroll
        for (int b = 0; b < 4; ++b)
#pragma unroll
            for (int c = 0; c < 4; ++c) acc[a][b][c] = 0.f;

    // Loader slot geometry (k0-independent):
    // A slot s (0..511): mtk=s>>5, ls=s&31 -> m_off=(mtk>>1)*16+(ls>>2), k_off=(mtk&1)*8+(ls&3)
    //   regs: +8 rows if reg&1, +4 cols if reg>>1
    // B slot s (0..1023): ntk=s>>5, ls=s&31 -> n_off=(ntk>>1)*8+(ls>>2), k_off=(ntk&1)*8+(ls&3)
    //   regs: +4 k if reg==1
    int amo[2], ako[2];
#pragma unroll
    for (int i = 0; i < 2; ++i) {
        int s = t + (i << 8), mtk = s >> 5, ls = s & 31;
        amo[i] = ((mtk >> 1) << 4) + (ls >> 2);
        ako[i] = ((mtk & 1) << 3) + (ls & 3);
    }
    int bno[4], bko[4];
#pragma unroll
    for (int i = 0; i < 4; ++i) {
        int s = t + (i << 8), ntk = s >> 5, ls = s & 31;
        bno[i] = ((ntk >> 1) << 3) + (ls >> 2);
        bko[i] = ((ntk & 1) << 3) + (ls & 3);
    }

    for (int k0 = 0; k0 < K; k0 += 16) {
        __syncthreads();
        // ---- A loader: split into (hi = rna-tf32, lo = v - hi) ----
#pragma unroll
        for (int i = 0; i < 2; ++i) {
            int s = t + (i << 8);
            const float* base = W + (size_t)(bm + amo[i]) * K + (k0 + ako[i]);
            float v0 = base[0];
            float v1 = base[(size_t)8 * K];
            float v2 = base[4];
            float v3 = base[(size_t)8 * K + 4];
            unsigned h0 = f2tf32(v0), h1 = f2tf32(v1), h2 = f2tf32(v2), h3 = f2tf32(v3);
            uint4 hv = {h0, h1, h2, h3};
            float4 lv = {v0 - __uint_as_float(h0), v1 - __uint_as_float(h1),
                         v2 - __uint_as_float(h2), v3 - __uint_as_float(h3)};
            *(uint4*)&Ah[s * 4] = hv;
            *(float4*)&Al[s * 4] = lv;
        }
        // ---- B loader ----
#pragma unroll
        for (int i = 0; i < 4; ++i) {
            int s = t + (i << 8);
            const float* base = Xb + (size_t)(k0 + bko[i]) * N + bn + bno[i];
            float v0 = base[0];
            float v1 = base[(size_t)4 * N];
            unsigned h0 = f2tf32(v0), h1 = f2tf32(v1);
            uint2 hv = {h0, h1};
            float2 lv = {v0 - __uint_as_float(h0), v1 - __uint_as_float(h1)};
            *(uint2*)&Bh[s * 2] = hv;
            *(float2*)&Bl[s * 2] = lv;
        }
        __syncthreads();

        // ---- compute: 2 k-steps, 4x4 warp tiles, 3 mma per tile ----
#pragma unroll
        for (int ks = 0; ks < 2; ++ks) {
            uint4 ah[4]; float4 al[4];
#pragma unroll
            for (int mt = 0; mt < 4; ++mt) {
                int idx = (((warpM * 4 + mt) * 2 + ks) * 32 + lane);
                ah[mt] = *(const uint4*)&Ah[idx * 4];
                al[mt] = *(const float4*)&Al[idx * 4];
            }
#pragma unroll
            for (int nt = 0; nt < 4; ++nt) {
                int idx = (((warpN * 4 + nt) * 2 + ks) * 32 + lane);
                uint2 bh = *(const uint2*)&Bh[idx * 2];
                float2 bl = *(const float2*)&Bl[idx * 2];
                unsigned bl0 = __float_as_uint(bl.x), bl1 = __float_as_uint(bl.y);
#pragma unroll
                for (int mt = 0; mt < 4; ++mt) {
                    float* c = acc[mt][nt];
                    // hi*hi
                    mma_tf32(c[0], c[1], c[2], c[3],
                             ah[mt].x, ah[mt].y, ah[mt].z, ah[mt].w, bh.x, bh.y);
                    // hi*lo
                    mma_tf32(c[0], c[1], c[2], c[3],
                             ah[mt].x, ah[mt].y, ah[mt].z, ah[mt].w, bl0, bl1);
                    // lo*hi
                    mma_tf32(c[0], c[1], c[2], c[3],
                             __float_as_uint(al[mt].x), __float_as_uint(al[mt].y),
                             __float_as_uint(al[mt].z), __float_as_uint(al[mt].w),
                             bh.x, bh.y);
                }
            }
        }
    }

    // ---- epilogue ----
    const int r = lane >> 2, j = lane & 3;
#pragma unroll
    for (int mt = 0; mt < 4; ++mt) {
        const int m0 = bm + warpM * 64 + mt * 16 + r;
        const float bv0 = bias ? bias[m0] : 0.f;
        const float bv1 = bias ? bias[m0 + 8] : 0.f;
#pragma unroll
        for (int nt = 0; nt < 4; ++nt) {
            const int n = bn + warpN * 32 + nt * 8 + j * 2;
            const float* c = acc[mt][nt];
            float r0 = alpha * c[0] + bv0, r1 = alpha * c[1] + bv0;
            float r2 = alpha * c[2] + bv1, r3 = alpha * c[3] + bv1;
            if (relu) {
                r0 = fmaxf(r0, 0.f); r1 = fmaxf(r1, 0.f);
                r2 = fmaxf(r2, 0.f); r3 = fmaxf(r3, 0.f);
            }
            float2 w0 = {r0, r1}, w1 = {r2, r3};
            *(float2*)&Cb[(size_t)m0 * N + n] = w0;
            *(float2*)&Cb[(size_t)(m0 + 8) * N + n] = w1;
        }
    }
}

// ---------------------------------------------------------------------------
// Flash attention (causal), fp32 scalar (round-1 numerics, known good).
// Both paths fused in one launch: z = path*BB + b.
// SMEM: Qs[64][128] | Ks[64][64] | Vt[64][68] | Ps[64][128]
// ---------------------------------------------------------------------------
#define ATTN_SMEM ((64*128 + 64*64 + 64*68 + 64*128) * 4)

__global__ __launch_bounds__(128) void attn_kernel(
    const float* __restrict__ Ql, const float* __restrict__ Kl,
    const float* __restrict__ Vl, float* __restrict__ Ol,
    const float* __restrict__ Qr, const float* __restrict__ Kr,
    const float* __restrict__ Vr, float* __restrict__ Or)
{
    extern __shared__ float sm[];
    float* Qs = sm;                  // [64][128]  Qs[d][q_local]
    float* Ks = sm + 64 * 128;       // [64][64]   Ks[d][t]
    float* Vt = Ks + 64 * 64;        // [64][68]   Vt[t][d] (pad 68)
    float* Ps = Vt + 64 * 68;        // [64][128]  Ps[t][q_local]

    const int tid = threadIdx.x;
    const int path = blockIdx.z >> 1;
    const int bz = blockIdx.z & 1;
    const float* Q = path ? Qr : Ql;
    const float* Kg = path ? Kr : Kl;
    const float* V = path ? Vr : Vl;
    float* O = path ? Or : Ol;

    const int qt = (gridDim.x - 1) - blockIdx.x;   // heavy tiles launch first
    const int q0 = qt << 7;
    const size_t base = ((size_t)bz * EE + (size_t)blockIdx.y * DD) * SS;
    const float* Qp = Q + base;
    const float* Kp = Kg + base;
    const float* Vp = V + base;
    const int q = q0 + tid;

    // load Q tile (scaling folded into projection GEMM)
    for (int f = tid; f < 64 * 32; f += 128) {
        int d = f >> 5, qc = (f & 31) << 2;
        *(float4*)&Qs[d * 128 + qc] =
            *(const float4*)&Qp[(size_t)d * SS + q0 + qc];
    }

    float o[64];
#pragma unroll
    for (int d = 0; d < 64; ++d) o[d] = 0.f;
    float mrow = -1e30f, lrow = 0.f;

    const int nt = qt * 2 + 2;
    for (int kt = 0; kt < nt; ++kt) {
        const int t0 = kt << 6;
        __syncthreads();
        for (int f = tid; f < 64 * 16; f += 128) {
            int d = f >> 4, tc = (f & 15) << 2;
            *(float4*)&Ks[d * 64 + tc] =
                *(const float4*)&Kp[(size_t)d * SS + t0 + tc];
        }
        for (int f = tid; f < 64 * 64; f += 128) {
            int d = f >> 6, tt = f & 63;
            Vt[tt * 68 + d] = Vp[(size_t)d * SS + t0 + tt];
        }
        __syncthreads();

        float s[64];
#pragma unroll
        for (int tt = 0; tt < 64; ++tt) s[tt] = 0.f;
#pragma unroll 4
        for (int d = 0; d < 64; ++d) {
            float qd = Qs[d * 128 + tid];
#pragma unroll
            for (int t4 = 0; t4 < 16; ++t4) {
                float4 k4 = *(const float4*)&Ks[d * 64 + (t4 << 2)];
                s[(t4 << 2) + 0] = fmaf(qd, k4.x, s[(t4 << 2) + 0]);
                s[(t4 << 2) + 1] = fmaf(qd, k4.y, s[(t4 << 2) + 1]);
                s[(t4 << 2) + 2] = fmaf(qd, k4.z, s[(t4 << 2) + 2]);
                s[(t4 << 2) + 3] = fmaf(qd, k4.w, s[(t4 << 2) + 3]);
            }
        }
#pragma unroll
        for (int tt = 0; tt < 64; ++tt)
            if (t0 + tt > q) s[tt] = -1e30f;

        float mx = mrow;
#pragma unroll
        for (int tt = 0; tt < 64; ++tt) mx = fmaxf(mx, s[tt]);
        float corr = __expf(mrow - mx);
        mrow = mx;
        lrow *= corr;
#pragma unroll
        for (int d = 0; d < 64; ++d) o[d] *= corr;
        float lsum = 0.f;
#pragma unroll
        for (int tt = 0; tt < 64; ++tt) {
            float p = __expf(s[tt] - mx);
            Ps[tt * 128 + tid] = p;
            lsum += p;
        }
        lrow += lsum;

        for (int tt = 0; tt < 64; ++tt) {
            float pt = Ps[tt * 128 + tid];
#pragma unroll
            for (int d4 = 0; d4 < 16; ++d4) {
                float4 v4 = *(const float4*)&Vt[tt * 68 + (d4 << 2)];
                o[(d4 << 2) + 0] = fmaf(pt, v4.x, o[(d4 << 2) + 0]);
                o[(d4 << 2) + 1] = fmaf(pt, v4.y, o[(d4 << 2) + 1]);
                o[(d4 << 2) + 2] = fmaf(pt, v4.z, o[(d4 << 2) + 2]);
                o[(d4 << 2) + 3] = fmaf(pt, v4.w, o[(d4 << 2) + 3]);
            }
        }
    }

    const float inv = 1.f / lrow;
    float* Op = O + base;
#pragma unroll
    for (int d = 0; d < 64; ++d)
        Op[(size_t)d * SS + q] = o[d] * inv;
}

// ---------------------------------------------------------------------------
// lambda = exp(sum lam_q_l*lam_k_l) - exp(sum lam_q_r*lam_k_r) + 0.1
// ---------------------------------------------------------------------------
__global__ void lam_kernel(const float* __restrict__ ql, const float* __restrict__ kl,
                           const float* __restrict__ qr, const float* __restrict__ kr)
{
    const int t = threadIdx.x;   // 32 threads
    float a = ql[t] * kl[t] + ql[t + 32] * kl[t + 32];
    float b = qr[t] * kr[t] + qr[t + 32] * kr[t + 32];
#pragma unroll
    for (int off = 16; off > 0; off >>= 1) {
        a += __shfl_xor_sync(0xffffffffu, a, off);
        b += __shfl_xor_sync(0xffffffffu, b, off);
    }
    if (t == 0) g_lam = expf(a) - expf(b) + 0.1f;
}

// ---------------------------------------------------------------------------
// combined = attn_l - lam*attn_r; LayerNorm over E (biased var, eps 1e-5).
// ---------------------------------------------------------------------------
__global__ __launch_bounds__(512) void ln_kernel(
    const float* __restrict__ al, const float* __restrict__ ar,
    const float* __restrict__ gg, const float* __restrict__ bbv,
    float* __restrict__ out)
{
    __shared__ float ps[16][32], pq[16][32], smu[32], srs[32];
    const int tid = threadIdx.x;
    const int ty = tid >> 5, sl = tid & 31;
    const int b = blockIdx.x >> 6;
    const int s = ((blockIdx.x & 63) << 5) + sl;
    const float lam = g_lam;
    const size_t col = (size_t)b * EE * SS + s;
    const int e0 = ty << 6;

    float sum = 0.f, sq = 0.f;
    for (int e = e0; e < e0 + 64; ++e) {
        size_t idx = col + (size_t)e * SS;
        float c = al[idx] - lam * ar[idx];
        sum += c; sq += c * c;
    }
    ps[ty][sl] = sum; pq[ty][sl] = sq;
    __syncthreads();
    if (ty == 0) {
        float ts = 0.f, tq = 0.f;
#pragma unroll
        for (int r = 0; r < 16; ++r) { ts += ps[r][sl]; tq += pq[r][sl]; }
        float mu = ts * (1.f / EE);
        float var = tq * (1.f / EE) - mu * mu;
        smu[sl] = mu;
        srs[sl] = rsqrtf(var + 1e-5f);
    }
    __syncthreads();
    const float mu = smu[sl], rs = srs[sl];
    for (int e = e0; e < e0 + 64; ++e) {
        size_t idx = col + (size_t)e * SS;
        float c = al[idx] - lam * ar[idx];
        out[idx] = (c - mu) * rs * gg[e] + bbv[e];
    }
}

// ---------------------------------------------------------------------------
// Launch
// ---------------------------------------------------------------------------
static float* sym_addr(const void* symbol)
{
    void* p = nullptr;
    cudaGetSymbolAddress(&p, symbol);
    return (float*)p;
}

extern "C" void kernel_launch(void* const* d_in, const int* in_sizes, int n_in,
                              void* d_out, int out_size)
{
    const float* left  = (const float*)d_in[0];
    const float* right = (const float*)d_in[1];
    const float* Wq_l  = (const float*)d_in[2];
    const float* Wk_l  = (const float*)d_in[3];
    const float* Wv_l  = (const float*)d_in[4];
    const float* Wq_r  = (const float*)d_in[5];
    const float* Wk_r  = (const float*)d_in[6];
    const float* Wv_r  = (const float*)d_in[7];
    const float* Wo    = (const float*)d_in[8];
    const float* lql   = (const float*)d_in[9];
    const float* lkl   = (const float*)d_in[10];
    const float* lqr   = (const float*)d_in[11];
    const float* lkr   = (const float*)d_in[12];
    const float* ln_g  = (const float*)d_in[13];
    const float* ln_b  = (const float*)d_in[14];
    const float* W1    = (const float*)d_in[15];
    const float* b1    = (const float*)d_in[16];
    const float* W2    = (const float*)d_in[17];
    const float* b2    = (const float*)d_in[18];
    float* out = (float*)d_out;

    float* ql = sym_addr(g_ql); float* kl = sym_addr(g_kl); float* vl = sym_addr(g_vl);
    float* qr = sym_addr(g_qr); float* kr = sym_addr(g_kr); float* vr = sym_addr(g_vr);
    float* al = sym_addr(g_al); float* ar = sym_addr(g_ar);
    float* lno = sym_addr(g_lnout); float* y = sym_addr(g_y);
    float* h1 = sym_addr(g_h1);

    const float qscale = 0.125f;   // D^-0.5 folded into q projection

    dim3 blk(256);
    dim3 gp(SS / 128, EE / 128, BB);         // (16, 8, 2)
    dim3 gp1(SS / 128, (2 * EE) / 128, BB);  // (16, 16, 2)

    // QKV projections (tensor-core 3xTF32, native [B,E,S] layout)
    gemm_tc<<<gp, blk>>>(Wq_l, left,  ql, EE, EE, SS, nullptr, qscale, 0);
    gemm_tc<<<gp, blk>>>(Wk_l, left,  kl, EE, EE, SS, nullptr, 1.f, 0);
    gemm_tc<<<gp, blk>>>(Wv_l, left,  vl, EE, EE, SS, nullptr, 1.f, 0);
    gemm_tc<<<gp, blk>>>(Wq_r, right, qr, EE, EE, SS, nullptr, qscale, 0);
    gemm_tc<<<gp, blk>>>(Wk_r, right, kr, EE, EE, SS, nullptr, 1.f, 0);
    gemm_tc<<<gp, blk>>>(Wv_r, right, vr, EE, EE, SS, nullptr, 1.f, 0);

    // attention: both paths in one launch (z = path*2 + b)
    cudaFuncSetAttribute(attn_kernel, cudaFuncAttributeMaxDynamicSharedMemorySize,
                         ATTN_SMEM);
    dim3 ga(SS / 128, HH, 2 * BB);           // (16, 16, 4)
    attn_kernel<<<ga, 128, ATTN_SMEM>>>(ql, kl, vl, al, qr, kr, vr, ar);

    // lambda, combine + LN
    lam_kernel<<<1, 32>>>(lql, lkl, lqr, lkr);
    ln_kernel<<<BB * (SS / 32), 512>>>(al, ar, ln_g, ln_b, lno);

    // output projection + MLP (W2 writes straight into d_out, already [B,E,S])
    gemm_tc<<<gp,  blk>>>(Wo, lno, y,   EE,     EE,     SS, nullptr, 1.f, 0);
    gemm_tc<<<gp1, blk>>>(W1, y,   h1,  2 * EE, EE,     SS, b1,      1.f, 1);
    gemm_tc<<<gp,  blk>>>(W2, h1,  out, EE,     2 * EE, SS, b2,      1.f, 0);
}

// round 4
// speedup vs baseline: 1.2376x; 1.1622x over previous
#include <cuda_runtime.h>
#include <math.h>

// Problem constants
#define BB 2
#define EE 1024
#define SS 2048
#define HH 16
#define DD 64
#define BES (BB*EE*SS)          // 4,194,304 elements

// ---------------------------------------------------------------------------
// Scratch (device globals; no runtime allocation allowed)
// ---------------------------------------------------------------------------
__device__ float g_ql[BES], g_kl[BES], g_vl[BES];
__device__ float g_qr[BES], g_kr[BES], g_vr[BES];
__device__ float g_al[BES], g_ar[BES];
__device__ float g_lnout[BES];
__device__ float g_h1[2 * BES];
__device__ float g_wf[2 * EE * EE];     // fused W1@Wo
__device__ float g_lam;

// ---------------------------------------------------------------------------
// TF32 helpers
// ---------------------------------------------------------------------------
__device__ __forceinline__ unsigned f2tf32(float v) {
    unsigned r; asm("cvt.rna.tf32.f32 %0, %1;" : "=r"(r) : "f"(v)); return r;
}
__device__ __forceinline__ void mma_tf32(
    float& c0, float& c1, float& c2, float& c3,
    unsigned a0, unsigned a1, unsigned a2, unsigned a3,
    unsigned b0, unsigned b1)
{
    asm("mma.sync.aligned.m16n8k8.row.col.f32.tf32.tf32.f32 "
        "{%0,%1,%2,%3}, {%4,%5,%6,%7}, {%8,%9}, {%0,%1,%2,%3};"
        : "+f"(c0), "+f"(c1), "+f"(c2), "+f"(c3)
        : "r"(a0), "r"(a1), "r"(a2), "r"(a3), "r"(b0), "r"(b1));
}

// ---------------------------------------------------------------------------
// Tensor-core GEMM (3xTF32), double-buffered software pipeline.
// C[b][m][n] = relu?(alpha*sum_k W[m][k]*X[b][k][n] + bias[m])
// Block tile 128x128, BK=16, 256 threads = 8 warps (2 warpM x 4 warpN),
// warp tile 64x32 = 4x4 m16n8k8 tiles. Fragments staged in SMEM in fragment
// order (conflict-free LDS.128/LDS.64, contiguous STS). Two 32KB SMEM buffers;
// next global tile is prefetched into registers during the current MMAs.
//
// Per-buffer word layout: Ah[0..2047] Al[2048..4095] Bh[4096..6143] Bl[6144..8191]
// ---------------------------------------------------------------------------
#define GEMM_SMEM (2 * 8192 * 4)

__global__ __launch_bounds__(256, 1) void gemm_tc(
    const float* __restrict__ W, const float* __restrict__ X,
    float* __restrict__ C, int M, int K, int N,
    const float* __restrict__ bias, float alpha, int relu)
{
    extern __shared__ __align__(16) unsigned smp[];   // 2 x 8192 words

    const int t = threadIdx.x;
    const int lane = t & 31, wid = t >> 5;
    const int warpM = wid >> 2, warpN = wid & 3;
    const int bm = blockIdx.y << 7, bn = blockIdx.x << 7;
    const float* Xb = X + (size_t)blockIdx.z * K * N;
    float* Cb = C + (size_t)blockIdx.z * M * N;

    float acc[4][4][4];   // [mt][nt][creg]
#pragma unroll
    for (int a = 0; a < 4; ++a)
#pragma unroll
        for (int b = 0; b < 4; ++b)
#pragma unroll
            for (int c = 0; c < 4; ++c) acc[a][b][c] = 0.f;

    // Loader slot geometry (k0-independent), identical to round-3 kernel:
    int amo[2], ako[2];
#pragma unroll
    for (int i = 0; i < 2; ++i) {
        int s = t + (i << 8), mtk = s >> 5, ls = s & 31;
        amo[i] = ((mtk >> 1) << 4) + (ls >> 2);
        ako[i] = ((mtk & 1) << 3) + (ls & 3);
    }
    int bno[4], bko[4];
#pragma unroll
    for (int i = 0; i < 4; ++i) {
        int s = t + (i << 8), ntk = s >> 5, ls = s & 31;
        bno[i] = ((ntk >> 1) << 3) + (ls >> 2);
        bko[i] = ((ntk & 1) << 3) + (ls & 3);
    }

    float pa[2][4];   // prefetched A values
    float pb[4][2];   // prefetched B values

    // ---- global load of tile at k0 into prefetch regs ----
    auto loadG = [&](int k0) {
#pragma unroll
        for (int i = 0; i < 2; ++i) {
            const float* base = W + (size_t)(bm + amo[i]) * K + (k0 + ako[i]);
            pa[i][0] = base[0];
            pa[i][1] = base[(size_t)8 * K];
            pa[i][2] = base[4];
            pa[i][3] = base[(size_t)8 * K + 4];
        }
#pragma unroll
        for (int i = 0; i < 4; ++i) {
            const float* base = Xb + (size_t)(k0 + bko[i]) * N + bn + bno[i];
            pb[i][0] = base[0];
            pb[i][1] = base[(size_t)4 * N];
        }
    };

    // ---- convert + store prefetch regs into SMEM buffer ----
    auto storeS = [&](int buf) {
        unsigned* Ah = smp + buf * 8192;
        float*    Al = (float*)(smp + buf * 8192 + 2048);
        unsigned* Bh = smp + buf * 8192 + 4096;
        float*    Bl = (float*)(smp + buf * 8192 + 6144);
#pragma unroll
        for (int i = 0; i < 2; ++i) {
            int s = t + (i << 8);
            unsigned h0 = f2tf32(pa[i][0]), h1 = f2tf32(pa[i][1]);
            unsigned h2 = f2tf32(pa[i][2]), h3 = f2tf32(pa[i][3]);
            uint4 hv = {h0, h1, h2, h3};
            float4 lv = {pa[i][0] - __uint_as_float(h0), pa[i][1] - __uint_as_float(h1),
                         pa[i][2] - __uint_as_float(h2), pa[i][3] - __uint_as_float(h3)};
            *(uint4*)&Ah[s * 4] = hv;
            *(float4*)&Al[s * 4] = lv;
        }
#pragma unroll
        for (int i = 0; i < 4; ++i) {
            int s = t + (i << 8);
            unsigned h0 = f2tf32(pb[i][0]), h1 = f2tf32(pb[i][1]);
            uint2 hv = {h0, h1};
            float2 lv = {pb[i][0] - __uint_as_float(h0), pb[i][1] - __uint_as_float(h1)};
            *(uint2*)&Bh[s * 2] = hv;
            *(float2*)&Bl[s * 2] = lv;
        }
    };

    // ---- MMA compute on SMEM buffer ----
    auto compute = [&](int buf) {
        const unsigned* Ah = smp + buf * 8192;
        const float*    Al = (const float*)(smp + buf * 8192 + 2048);
        const unsigned* Bh = smp + buf * 8192 + 4096;
        const float*    Bl = (const float*)(smp + buf * 8192 + 6144);
#pragma unroll
        for (int ks = 0; ks < 2; ++ks) {
            uint4 ah[4]; float4 al[4];
#pragma unroll
            for (int mt = 0; mt < 4; ++mt) {
                int idx = (((warpM * 4 + mt) * 2 + ks) * 32 + lane);
                ah[mt] = *(const uint4*)&Ah[idx * 4];
                al[mt] = *(const float4*)&Al[idx * 4];
            }
#pragma unroll
            for (int nt = 0; nt < 4; ++nt) {
                int idx = (((warpN * 4 + nt) * 2 + ks) * 32 + lane);
                uint2 bh = *(const uint2*)&Bh[idx * 2];
                float2 bl = *(const float2*)&Bl[idx * 2];
                unsigned bl0 = __float_as_uint(bl.x), bl1 = __float_as_uint(bl.y);
#pragma unroll
                for (int mt = 0; mt < 4; ++mt) {
                    float* c = acc[mt][nt];
                    mma_tf32(c[0], c[1], c[2], c[3],
                             ah[mt].x, ah[mt].y, ah[mt].z, ah[mt].w, bh.x, bh.y);
                    mma_tf32(c[0], c[1], c[2], c[3],
                             ah[mt].x, ah[mt].y, ah[mt].z, ah[mt].w, bl0, bl1);
                    mma_tf32(c[0], c[1], c[2], c[3],
                             __float_as_uint(al[mt].x), __float_as_uint(al[mt].y),
                             __float_as_uint(al[mt].z), __float_as_uint(al[mt].w),
                             bh.x, bh.y);
                }
            }
        }
    };

    // ---- pipelined main loop ----
    const int kiters = K >> 4;
    loadG(0);
    storeS(0);
    __syncthreads();
    for (int it = 0; it < kiters; ++it) {
        const int cur = it & 1;
        if (it + 1 < kiters) loadG((it + 1) << 4);   // LDGs fly during MMAs
        compute(cur);
        if (it + 1 < kiters) storeS(cur ^ 1);
        __syncthreads();
    }

    // ---- epilogue ----
    const int r = lane >> 2, j = lane & 3;
#pragma unroll
    for (int mt = 0; mt < 4; ++mt) {
        const int m0 = bm + warpM * 64 + mt * 16 + r;
        const float bv0 = bias ? bias[m0] : 0.f;
        const float bv1 = bias ? bias[m0 + 8] : 0.f;
#pragma unroll
        for (int nt = 0; nt < 4; ++nt) {
            const int n = bn + warpN * 32 + nt * 8 + j * 2;
            const float* c = acc[mt][nt];
            float r0 = alpha * c[0] + bv0, r1 = alpha * c[1] + bv0;
            float r2 = alpha * c[2] + bv1, r3 = alpha * c[3] + bv1;
            if (relu) {
                r0 = fmaxf(r0, 0.f); r1 = fmaxf(r1, 0.f);
                r2 = fmaxf(r2, 0.f); r3 = fmaxf(r3, 0.f);
            }
            float2 w0 = {r0, r1}, w1 = {r2, r3};
            *(float2*)&Cb[(size_t)m0 * N + n] = w0;
            *(float2*)&Cb[(size_t)(m0 + 8) * N + n] = w1;
        }
    }
}

// ---------------------------------------------------------------------------
// Flash attention (causal), fp32 scalar (known-good numerics).
// Both paths fused in one launch: z = path*BB + b.
// SMEM: Qs[64][128] | Ks[64][64] | Vt[64][68] | Ps[64][128]
// ---------------------------------------------------------------------------
#define ATTN_SMEM ((64*128 + 64*64 + 64*68 + 64*128) * 4)

__global__ __launch_bounds__(128) void attn_kernel(
    const float* __restrict__ Ql, const float* __restrict__ Kl,
    const float* __restrict__ Vl, float* __restrict__ Ol,
    const float* __restrict__ Qr, const float* __restrict__ Kr,
    const float* __restrict__ Vr, float* __restrict__ Or)
{
    extern __shared__ float sm[];
    float* Qs = sm;                  // [64][128]  Qs[d][q_local]
    float* Ks = sm + 64 * 128;       // [64][64]   Ks[d][t]
    float* Vt = Ks + 64 * 64;        // [64][68]   Vt[t][d] (pad 68)
    float* Ps = Vt + 64 * 68;        // [64][128]  Ps[t][q_local]

    const int tid = threadIdx.x;
    const int path = blockIdx.z >> 1;
    const int bz = blockIdx.z & 1;
    const float* Q = path ? Qr : Ql;
    const float* Kg = path ? Kr : Kl;
    const float* V = path ? Vr : Vl;
    float* O = path ? Or : Ol;

    const int qt = (gridDim.x - 1) - blockIdx.x;   // heavy tiles launch first
    const int q0 = qt << 7;
    const size_t base = ((size_t)bz * EE + (size_t)blockIdx.y * DD) * SS;
    const float* Qp = Q + base;
    const float* Kp = Kg + base;
    const float* Vp = V + base;
    const int q = q0 + tid;

    for (int f = tid; f < 64 * 32; f += 128) {
        int d = f >> 5, qc = (f & 31) << 2;
        *(float4*)&Qs[d * 128 + qc] =
            *(const float4*)&Qp[(size_t)d * SS + q0 + qc];
    }

    float o[64];
#pragma unroll
    for (int d = 0; d < 64; ++d) o[d] = 0.f;
    float mrow = -1e30f, lrow = 0.f;

    const int nt = qt * 2 + 2;
    for (int kt = 0; kt < nt; ++kt) {
        const int t0 = kt << 6;
        __syncthreads();
        for (int f = tid; f < 64 * 16; f += 128) {
            int d = f >> 4, tc = (f & 15) << 2;
            *(float4*)&Ks[d * 64 + tc] =
                *(const float4*)&Kp[(size_t)d * SS + t0 + tc];
        }
        for (int f = tid; f < 64 * 64; f += 128) {
            int d = f >> 6, tt = f & 63;
            Vt[tt * 68 + d] = Vp[(size_t)d * SS + t0 + tt];
        }
        __syncthreads();

        float s[64];
#pragma unroll
        for (int tt = 0; tt < 64; ++tt) s[tt] = 0.f;
#pragma unroll 4
        for (int d = 0; d < 64; ++d) {
            float qd = Qs[d * 128 + tid];
#pragma unroll
            for (int t4 = 0; t4 < 16; ++t4) {
                float4 k4 = *(const float4*)&Ks[d * 64 + (t4 << 2)];
                s[(t4 << 2) + 0] = fmaf(qd, k4.x, s[(t4 << 2) + 0]);
                s[(t4 << 2) + 1] = fmaf(qd, k4.y, s[(t4 << 2) + 1]);
                s[(t4 << 2) + 2] = fmaf(qd, k4.z, s[(t4 << 2) + 2]);
                s[(t4 << 2) + 3] = fmaf(qd, k4.w, s[(t4 << 2) + 3]);
            }
        }
#pragma unroll
        for (int tt = 0; tt < 64; ++tt)
            if (t0 + tt > q) s[tt] = -1e30f;

        float mx = mrow;
#pragma unroll
        for (int tt = 0; tt < 64; ++tt) mx = fmaxf(mx, s[tt]);
        float corr = __expf(mrow - mx);
        mrow = mx;
        lrow *= corr;
#pragma unroll
        for (int d = 0; d < 64; ++d) o[d] *= corr;
        float lsum = 0.f;
#pragma unroll
        for (int tt = 0; tt < 64; ++tt) {
            float p = __expf(s[tt] - mx);
            Ps[tt * 128 + tid] = p;
            lsum += p;
        }
        lrow += lsum;

        for (int tt = 0; tt < 64; ++tt) {
            float pt = Ps[tt * 128 + tid];
#pragma unroll
            for (int d4 = 0; d4 < 16; ++d4) {
                float4 v4 = *(const float4*)&Vt[tt * 68 + (d4 << 2)];
                o[(d4 << 2) + 0] = fmaf(pt, v4.x, o[(d4 << 2) + 0]);
                o[(d4 << 2) + 1] = fmaf(pt, v4.y, o[(d4 << 2) + 1]);
                o[(d4 << 2) + 2] = fmaf(pt, v4.z, o[(d4 << 2) + 2]);
                o[(d4 << 2) + 3] = fmaf(pt, v4.w, o[(d4 << 2) + 3]);
            }
        }
    }

    const float inv = 1.f / lrow;
    float* Op = O + base;
#pragma unroll
    for (int d = 0; d < 64; ++d)
        Op[(size_t)d * SS + q] = o[d] * inv;
}

// ---------------------------------------------------------------------------
// lambda = exp(sum lam_q_l*lam_k_l) - exp(sum lam_q_r*lam_k_r) + 0.1
// ---------------------------------------------------------------------------
__global__ void lam_kernel(const float* __restrict__ ql, const float* __restrict__ kl,
                           const float* __restrict__ qr, const float* __restrict__ kr)
{
    const int t = threadIdx.x;   // 32 threads
    float a = ql[t] * kl[t] + ql[t + 32] * kl[t + 32];
    float b = qr[t] * kr[t] + qr[t + 32] * kr[t + 32];
#pragma unroll
    for (int off = 16; off > 0; off >>= 1) {
        a += __shfl_xor_sync(0xffffffffu, a, off);
        b += __shfl_xor_sync(0xffffffffu, b, off);
    }
    if (t == 0) g_lam = expf(a) - expf(b) + 0.1f;
}

// ---------------------------------------------------------------------------
// combined = attn_l - lam*attn_r; LayerNorm over E (biased var, eps 1e-5).
// ---------------------------------------------------------------------------
__global__ __launch_bounds__(512) void ln_kernel(
    const float* __restrict__ al, const float* __restrict__ ar,
    const float* __restrict__ gg, const float* __restrict__ bbv,
    float* __restrict__ out)
{
    __shared__ float ps[16][32], pq[16][32], smu[32], srs[32];
    const int tid = threadIdx.x;
    const int ty = tid >> 5, sl = tid & 31;
    const int b = blockIdx.x >> 6;
    const int s = ((blockIdx.x & 63) << 5) + sl;
    const float lam = g_lam;
    const size_t col = (size_t)b * EE * SS + s;
    const int e0 = ty << 6;

    float sum = 0.f, sq = 0.f;
    for (int e = e0; e < e0 + 64; ++e) {
        size_t idx = col + (size_t)e * SS;
        float c = al[idx] - lam * ar[idx];
        sum += c; sq += c * c;
    }
    ps[ty][sl] = sum; pq[ty][sl] = sq;
    __syncthreads();
    if (ty == 0) {
        float ts = 0.f, tq = 0.f;
#pragma unroll
        for (int r = 0; r < 16; ++r) { ts += ps[r][sl]; tq += pq[r][sl]; }
        float mu = ts * (1.f / EE);
        float var = tq * (1.f / EE) - mu * mu;
        smu[sl] = mu;
        srs[sl] = rsqrtf(var + 1e-5f);
    }
    __syncthreads();
    const float mu = smu[sl], rs = srs[sl];
    for (int e = e0; e < e0 + 64; ++e) {
        size_t idx = col + (size_t)e * SS;
        float c = al[idx] - lam * ar[idx];
        out[idx] = (c - mu) * rs * gg[e] + bbv[e];
    }
}

// ---------------------------------------------------------------------------
// Launch
// ---------------------------------------------------------------------------
static float* sym_addr(const void* symbol)
{
    void* p = nullptr;
    cudaGetSymbolAddress(&p, symbol);
    return (float*)p;
}

extern "C" void kernel_launch(void* const* d_in, const int* in_sizes, int n_in,
                              void* d_out, int out_size)
{
    const float* left  = (const float*)d_in[0];
    const float* right = (const float*)d_in[1];
    const float* Wq_l  = (const float*)d_in[2];
    const float* Wk_l  = (const float*)d_in[3];
    const float* Wv_l  = (const float*)d_in[4];
    const float* Wq_r  = (const float*)d_in[5];
    const float* Wk_r  = (const float*)d_in[6];
    const float* Wv_r  = (const float*)d_in[7];
    const float* Wo    = (const float*)d_in[8];
    const float* lql   = (const float*)d_in[9];
    const float* lkl   = (const float*)d_in[10];
    const float* lqr   = (const float*)d_in[11];
    const float* lkr   = (const float*)d_in[12];
    const float* ln_g  = (const float*)d_in[13];
    const float* ln_b  = (const float*)d_in[14];
    const float* W1    = (const float*)d_in[15];
    const float* b1    = (const float*)d_in[16];
    const float* W2    = (const float*)d_in[17];
    const float* b2    = (const float*)d_in[18];
    float* out = (float*)d_out;

    float* ql = sym_addr(g_ql); float* kl = sym_addr(g_kl); float* vl = sym_addr(g_vl);
    float* qr = sym_addr(g_qr); float* kr = sym_addr(g_kr); float* vr = sym_addr(g_vr);
    float* al = sym_addr(g_al); float* ar = sym_addr(g_ar);
    float* lno = sym_addr(g_lnout);
    float* h1 = sym_addr(g_h1);
    float* wf = sym_addr(g_wf);

    const float qscale = 0.125f;   // D^-0.5 folded into q projection

    cudaFuncSetAttribute(gemm_tc, cudaFuncAttributeMaxDynamicSharedMemorySize,
                         GEMM_SMEM);
    cudaFuncSetAttribute(attn_kernel, cudaFuncAttributeMaxDynamicSharedMemorySize,
                         ATTN_SMEM);

    dim3 blk(256);
    dim3 gp(SS / 128, EE / 128, BB);         // (16, 8, 2)
    dim3 gp1(SS / 128, (2 * EE) / 128, BB);  // (16, 16, 2)
    dim3 gpw(EE / 128, (2 * EE) / 128, 1);   // Wf = W1 @ Wo precompute

    // Wf precompute early (independent of activations)
    gemm_tc<<<gpw, blk, GEMM_SMEM>>>(W1, Wo, wf, 2 * EE, EE, EE, nullptr, 1.f, 0);

    // QKV projections (tensor-core 3xTF32, native [B,E,S] layout)
    gemm_tc<<<gp, blk, GEMM_SMEM>>>(Wq_l, left,  ql, EE, EE, SS, nullptr, qscale, 0);
    gemm_tc<<<gp, blk, GEMM_SMEM>>>(Wk_l, left,  kl, EE, EE, SS, nullptr, 1.f, 0);
    gemm_tc<<<gp, blk, GEMM_SMEM>>>(Wv_l, left,  vl, EE, EE, SS, nullptr, 1.f, 0);
    gemm_tc<<<gp, blk, GEMM_SMEM>>>(Wq_r, right, qr, EE, EE, SS, nullptr, qscale, 0);
    gemm_tc<<<gp, blk, GEMM_SMEM>>>(Wk_r, right, kr, EE, EE, SS, nullptr, 1.f, 0);
    gemm_tc<<<gp, blk, GEMM_SMEM>>>(Wv_r, right, vr, EE, EE, SS, nullptr, 1.f, 0);

    // attention: both paths in one launch (z = path*2 + b)
    dim3 ga(SS / 128, HH, 2 * BB);           // (16, 16, 4)
    attn_kernel<<<ga, 128, ATTN_SMEM>>>(ql, kl, vl, al, qr, kr, vr, ar);

    // lambda, combine + LN
    lam_kernel<<<1, 32>>>(lql, lkl, lqr, lkr);
    ln_kernel<<<BB * (SS / 32), 512>>>(al, ar, ln_g, ln_b, lno);

    // fused (W1@Wo) + relu, then W2 straight into d_out ([B,E,S])
    gemm_tc<<<gp1, blk, GEMM_SMEM>>>(wf, lno, h1,  2 * EE, EE,     SS, b1, 1.f, 1);
    gemm_tc<<<gp,  blk, GEMM_SMEM>>>(W2, h1,  out, EE,     2 * EE, SS, b2, 1.f, 0);
}